// round 17
// baseline (speedup 1.0000x reference)
#include <cuda_runtime.h>
#include <math.h>

#define N_CLUSTS 50000

// Static device scratch (allowed; cudaMalloc is not)
__device__ float4 g_acc[N_CLUSTS * 3];   // [sx,sy,sz,cnt] [sxx,sxy,sxz,syy] [syz,szz,-,-]
__device__ float  g_sc[N_CLUSTS];        // sum x0*np0 (zeroed in P2)
__device__ int    g_bar[4];              // grid-barrier counters (memset each launch)

// One 32B record per cluster: {cx,cy,cz,dirwt, v0x,v0y,v0z,cnt}
struct __align__(32) CV {
    float4 ct;   // cx, cy, cz, dirwt
    float4 vv;   // v0x, v0y, v0z, cnt
};
__device__ CV g_cv[N_CLUSTS];

// Vectorized global reductions (ptxas-validated: .v2/.v4 only, 128-bit max).
__device__ __forceinline__ void red_add_v4(float4* addr, float a, float b, float c, float d) {
    asm volatile("red.global.add.v4.f32 [%0], {%1,%2,%3,%4};"
                 :: "l"(addr), "f"(a), "f"(b), "f"(c), "f"(d) : "memory");
}
__device__ __forceinline__ void red_add_v2(float4* addr, float a, float b) {
    asm volatile("red.global.add.v2.f32 [%0], {%1,%2};"
                 :: "l"(addr), "f"(a), "f"(b) : "memory");
}

// Software grid barrier. All blocks are guaranteed co-resident (grid sized by
// occupancy query). Release fence (gpu-scope -> CCTL.IVALL) before arrive;
// acquire fence after the poll so post-barrier plain loads see peer writes.
__device__ __forceinline__ void grid_barrier(int idx, int nblocks) {
    __syncthreads();
    if (threadIdx.x == 0) {
        __threadfence();                       // release my reds/stores
        atomicAdd(&g_bar[idx], 1);
        while (((volatile int*)g_bar)[idx] < nblocks) __nanosleep(128);
        __threadfence();                       // acquire: invalidate L1
    }
    __syncthreads();
}

// ---------------------------------------------------------------------------
// Fused persistent kernel: accum -> eig -> sc -> final with 3 grid barriers.
__global__ void __launch_bounds__(256, 3)
k_fused(const float* __restrict__ data, const int* __restrict__ cid,
        float* __restrict__ out, int n, int nblocks) {
    const int gsize = nblocks * 256;
    const int gtid  = blockIdx.x * 256 + threadIdx.x;

    // ---- P1: count + raw moments (3 vector reds/voxel — ISA floor) ----
    for (int i = gtid; i < n; i += gsize) {
        int c = __ldg(cid + i);
        const float* p = data + (size_t)i * 6;
        float  x  = __ldg(p + 1);
        float2 yz = __ldg((const float2*)(p + 2));   // 8B-aligned: 6i+2 even
        float  y = yz.x, z = yz.y;
        float4* acc = &g_acc[c * 3];
        red_add_v4(acc,     x,     y,     z,     1.0f);
        red_add_v4(acc + 1, x * x, x * y, x * z, y * y);
        red_add_v2(acc + 2, y * z, z * z);
    }
    grid_barrier(0, nblocks);

    // ---- P2: per-cluster eigensolve (plain loads: g_acc written by P1 reds) ----
    for (int c = gtid; c < N_CLUSTS; c += gsize) {
        g_sc[c] = 0.f;

        float4 s0 = g_acc[c * 3 + 0];
        float4 s1 = g_acc[c * 3 + 1];
        float4 s2 = g_acc[c * 3 + 2];
        float cnt = s0.w;
        float inv = 1.f / fmaxf(cnt, 1.f);
        float cx = s0.x * inv, cy = s0.y * inv, cz = s0.z * inv;

        float a00 = s1.x - cnt * cx * cx;
        float a01 = s1.y - cnt * cx * cy;
        float a02 = s1.z - cnt * cx * cz;
        float a11 = s1.w - cnt * cy * cy;
        float a12 = s2.x - cnt * cy * cz;
        float a22 = s2.y - cnt * cz * cz;

        // cyclic Jacobi, 5 sweeps (converged; validated rounds 12/13/15)
        float A[3][3] = {{a00, a01, a02}, {a01, a11, a12}, {a02, a12, a22}};
        float V[3][3] = {{1.f, 0.f, 0.f}, {0.f, 1.f, 0.f}, {0.f, 0.f, 1.f}};
        const int Pp[3] = {0, 0, 1};
        const int Qq[3] = {1, 2, 2};
        #pragma unroll 1
        for (int sweep = 0; sweep < 5; sweep++) {
            #pragma unroll
            for (int r = 0; r < 3; r++) {
                int p = Pp[r], q = Qq[r];
                float apq = A[p][q];
                if (fabsf(apq) > 0.f) {
                    float tau = (A[q][q] - A[p][p]) / (2.f * apq);
                    float t = copysignf(1.f / (fabsf(tau) + sqrtf(1.f + tau * tau)), tau);
                    float cth = rsqrtf(1.f + t * t);
                    float sth = t * cth;
                    #pragma unroll
                    for (int k = 0; k < 3; k++) {
                        float akp = A[k][p], akq = A[k][q];
                        A[k][p] = cth * akp - sth * akq;
                        A[k][q] = sth * akp + cth * akq;
                    }
                    #pragma unroll
                    for (int k = 0; k < 3; k++) {
                        float apk = A[p][k], aqk = A[q][k];
                        A[p][k] = cth * apk - sth * aqk;
                        A[q][k] = sth * apk + cth * aqk;
                    }
                    #pragma unroll
                    for (int k = 0; k < 3; k++) {
                        float vkp = V[k][p], vkq = V[k][q];
                        V[k][p] = cth * vkp - sth * vkq;
                        V[k][q] = sth * vkp + cth * vkq;
                    }
                }
            }
        }

        float w0 = A[0][0], w1 = A[1][1], w2 = A[2][2];
        int i2 = (w1 > w0) ? 1 : 0;
        float wt = (w1 > w0) ? w1 : w0;
        if (w2 > wt) { i2 = 2; wt = w2; }
        float wa, wb;
        if (i2 == 0)      { wa = w1; wb = w2; }
        else if (i2 == 1) { wa = w0; wb = w2; }
        else              { wa = w0; wb = w1; }
        float wmid = fmaxf(wa, wb);

        float safe = (wt > 0.f) ? wt : 1.f;
        float dirwt = 1.f - wmid / safe;
        bool multi = (cnt >= 2.f);
        float bm = multi ? (1.f / safe) : 0.f;

        float v0x = V[0][i2], v0y = V[1][i2], v0z = V[2][i2];

        float4* o4 = (float4*)(out + (size_t)c * 16);
        o4[0] = make_float4(cx, cy, cz, a00 * bm);
        o4[1] = make_float4(a01 * bm, a02 * bm, a01 * bm, a11 * bm);
        o4[2] = make_float4(a12 * bm, a02 * bm, a12 * bm, a22 * bm);

        CV cv;
        cv.ct = make_float4(cx, cy, cz, dirwt);
        cv.vv = make_float4(v0x, v0y, v0z, cnt);
        g_cv[c] = cv;
    }
    grid_barrier(1, nblocks);

    // ---- P3: sc pass (PLAIN g_cv loads — .nc illegal for same-kernel writes) ----
    for (int i = gtid; i < n; i += gsize) {
        int c = __ldg(cid + i);
        const float* p = data + (size_t)i * 6;
        float  x  = __ldg(p + 1);
        float2 yz = __ldg((const float2*)(p + 2));
        CV cv = g_cv[c];                       // two LDG.E.128 from one 32B sector
        float dx = x - cv.ct.x, dy = yz.x - cv.ct.y, dz = yz.y - cv.ct.z;
        float x0 = dx * cv.vv.x + dy * cv.vv.y + dz * cv.vv.z;
        float px = dx - x0 * cv.vv.x;
        float py = dy - x0 * cv.vv.y;
        float pz = dz - x0 * cv.vv.z;
        float np0 = sqrtf(px * px + py * py + pz * pz);
        atomicAdd(&g_sc[c], x0 * np0);
    }
    grid_barrier(2, nblocks);

    // ---- P4: finalize o[12..15] as one STG.128 ----
    for (int c = gtid; c < N_CLUSTS; c += gsize) {
        float sc = g_sc[c];
        CV cv = g_cv[c];
        float cnt = cv.vv.w;
        float s = (sc < 0.f) ? -1.f : 1.f;
        float f = s * cv.ct.w * ((cnt >= 2.f) ? 1.f : 0.f);
        float4* o4 = (float4*)(out + (size_t)c * 16);
        o4[3] = make_float4(cv.vv.x * f, cv.vv.y * f, cv.vv.z * f, cnt);
    }
}

// ---------------------------------------------------------------------------
extern "C" void kernel_launch(void* const* d_in, const int* in_sizes, int n_in,
                              void* d_out, int out_size) {
    const float* data = (const float*)d_in[0];
    const int*   cid  = (const int*)d_in[1];
    float* out = (float*)d_out;
    int n = in_sizes[1];   // number of voxels

    // Grid sized so ALL blocks are co-resident (barrier deadlock-free).
    int sms = 148, maxb = 3;
    cudaDeviceGetAttribute(&sms, cudaDevAttrMultiProcessorCount, 0);
    cudaOccupancyMaxActiveBlocksPerMultiprocessor(&maxb, k_fused, 256, 0);
    if (maxb < 1) maxb = 1;
    int nblocks = sms * maxb;

    // Zero accumulators + barrier counters via graph-capturable memset nodes.
    void* p_acc = nullptr;
    void* p_bar = nullptr;
    cudaGetSymbolAddress(&p_acc, g_acc);
    cudaGetSymbolAddress(&p_bar, g_bar);
    cudaMemsetAsync(p_acc, 0, sizeof(float4) * N_CLUSTS * 3, 0);
    cudaMemsetAsync(p_bar, 0, sizeof(int) * 4, 0);

    k_fused<<<nblocks, 256>>>(data, cid, out, n, nblocks);
}